// round 11
// baseline (speedup 1.0000x reference)
#include <cuda_runtime.h>
#include <cstdint>

// dct: [16, 64, 256, 256] fp32, mean/std: [64] fp32, out: [16, 1, 2048, 2048] fp32
#define HW      65536        // 256*256
#define OUTW    2048

// Dynamic smem (floats): sbuf [8 chunks][8 ch][256 pos] + tables
#define SBUF_FLOATS   16384
#define SMEM_FLOATS   (SBUF_FLOATS + 192)
#define SMEM_BYTES    (SMEM_FLOATS * 4)

__device__ __forceinline__ void cp_async16(uint32_t dst, const void* src) {
    asm volatile("cp.async.cg.shared.global [%0], [%1], 16;" :: "r"(dst), "l"(src));
}
__device__ __forceinline__ void cp_commit() {
    asm volatile("cp.async.commit_group;");
}
template <int N>
__device__ __forceinline__ void cp_wait() {
    asm volatile("cp.async.wait_group %0;" :: "n"(N) : "memory");
}

// Warp-private chunk issue: warp copies the 64 x 128B segments covering its
// 32 positions across channels c*8..c*8+7 into its stripe of slot `c`.
// Unit m: channel c*8 + (m>>3), float col within warp stripe = (m&7)*4.
__device__ __forceinline__ void issue_chunk(
    uint32_t sb, const float* src_w, int warp, int lane, int c)
{
    #pragma unroll
    for (int k = 0; k < 2; k++) {
        int m = lane + k * 32;
        const float* g = src_w + (size_t)(c * 8 + (m >> 3)) * HW + (m & 7) * 4;
        cp_async16(sb + (uint32_t)((c * 2048 + (m >> 3) * 256 + warp * 32 + (m & 7) * 4) * 4), g);
    }
}

// Consume chunk U. WAIT = wait_group bound. If src_next != nullptr, refill
// this warp's stripe of slot U with the next tile's chunk U (after the
// destandardize FMAs, whose operand dependencies guarantee the LDS of slot U
// completed; in-order issue then makes the refill safe). Always commits a
// group to keep the 8-group invariant.
template <int U, int WAIT>
__device__ __forceinline__ void consume_chunk(
    const float* sbuf, uint32_t sb, const float* src_next,
    const float* s_hx, const float* s_hy,
    const float* s_std, const float* s_mean,
    int tid, int warp, int lane, float E[4][8], float O[4][8])
{
    cp_wait<WAIT>();
    __syncwarp();      // cross-lane visibility within the warp's stripe

    float t[8];
    #pragma unroll
    for (int v = 0; v < 8; v++)
        t[v] = sbuf[U * 2048 + v * 256 + tid];
    #pragma unroll
    for (int v = 0; v < 8; v++)
        t[v] = fmaf(t[v], s_std[U * 8 + v], s_mean[U * 8 + v]);

    if (src_next) { issue_chunk(sb, src_next, warp, lane, U); }
    cp_commit();

    float ty[8];
    #pragma unroll
    for (int yp = 0; yp < 4; yp++) {
        float te = 0.0f, to = 0.0f;
        #pragma unroll
        for (int vp = 0; vp < 4; vp++) {
            te = fmaf(s_hy[(2 * vp    ) * 4 + yp], t[2 * vp    ], te);
            to = fmaf(s_hy[(2 * vp + 1) * 4 + yp], t[2 * vp + 1], to);
        }
        ty[yp]     = te + to;
        ty[7 - yp] = te - to;
    }

    #pragma unroll
    for (int xp = 0; xp < 4; xp++) {
        float w = s_hx[U * 4 + xp];
        if ((U & 1) == 0) {
            #pragma unroll
            for (int y = 0; y < 8; y++) E[xp][y] = fmaf(w, ty[y], E[xp][y]);
        } else {
            #pragma unroll
            for (int y = 0; y < 8; y++) O[xp][y] = fmaf(w, ty[y], O[xp][y]);
        }
    }
}

__device__ __forceinline__ void store_block(
    float* __restrict__ out, unsigned gid, float E[4][8], float O[4][8])
{
    unsigned b   = gid >> 16;
    unsigned pos = gid & 65535u;
    unsigned hh = pos >> 8, ww = pos & 255u;
    float* dst = out + (size_t)b * ((size_t)OUTW * OUTW)
                     + (size_t)hh * 8 * OUTW + (size_t)ww * 8;

    #pragma unroll
    for (int xp = 0; xp < 4; xp++) {
        float4 a, bq;
        a.x  = E[xp][0] + O[xp][0];  a.y  = E[xp][1] + O[xp][1];
        a.z  = E[xp][2] + O[xp][2];  a.w  = E[xp][3] + O[xp][3];
        bq.x = E[xp][4] + O[xp][4];  bq.y = E[xp][5] + O[xp][5];
        bq.z = E[xp][6] + O[xp][6];  bq.w = E[xp][7] + O[xp][7];
        *(float4*)(dst + (size_t)xp * OUTW)     = a;
        *(float4*)(dst + (size_t)xp * OUTW + 4) = bq;

        float4 c4, d4;
        c4.x = E[xp][0] - O[xp][0];  c4.y = E[xp][1] - O[xp][1];
        c4.z = E[xp][2] - O[xp][2];  c4.w = E[xp][3] - O[xp][3];
        d4.x = E[xp][4] - O[xp][4];  d4.y = E[xp][5] - O[xp][5];
        d4.z = E[xp][6] - O[xp][6];  d4.w = E[xp][7] - O[xp][7];
        *(float4*)(dst + (size_t)(7 - xp) * OUTW)     = c4;
        *(float4*)(dst + (size_t)(7 - xp) * OUTW + 4) = d4;
    }
}

__global__ __launch_bounds__(256, 2) void idct_kernel(
    const float* __restrict__ dct,
    const float* __restrict__ mean_,
    const float* __restrict__ std_,
    float* __restrict__ out)
{
    extern __shared__ float smem[];
    float* sbuf   = smem;                      // [8][8][256]
    float* s_hx   = smem + SBUF_FLOATS;        // [8][4]
    float* s_hy   = s_hx + 32;                 // [8][4]
    float* s_std  = s_hy + 32;                 // [64]
    float* s_mean = s_std + 64;                // [64]

    int tid  = threadIdx.x;
    int warp = tid >> 5, lane = tid & 31;
    uint32_t sb = (uint32_t)__cvta_generic_to_shared(sbuf);

    // Two adjacent 256-position tiles per CTA.
    unsigned tA = blockIdx.x * 2u, tB = tA + 1u;
    unsigned gidA = tA * 256u + (unsigned)tid;
    unsigned gidB = tB * 256u + (unsigned)tid;

    // Warp-uniform source pointers (per tile).
    unsigned baseA = tA * 256u + (unsigned)(warp * 32);
    unsigned baseB = tB * 256u + (unsigned)(warp * 32);
    const float* srcA = dct + (size_t)(baseA >> 16) * 64u * HW + (baseA & 65535u);
    const float* srcB = dct + (size_t)(baseB >> 16) * 64u * HW + (baseB & 65535u);

    // Prologue: tile A fully in flight (8 groups, 64KB/CTA).
    #pragma unroll
    for (int c = 0; c < 8; c++) { issue_chunk(sb, srcA, warp, lane, c); cp_commit(); }

    // Tables (overlap with copies); single barrier, doesn't drain groups.
    if (tid < 64) {
        int u = tid >> 3, x = tid & 7;
        float c = (u == 0) ? 0.70710678118654752440f : 1.0f;
        float h = cospif((float)((2 * x + 1) * u) * (1.0f / 16.0f));
        float v = 0.5f * c * h;
        if (x < 4) {
            s_hx[u * 4 + x] = v;
            s_hy[u * 4 + x] = v * (1.0f / 255.0f);
        }
        s_std[tid]  = std_[tid];
        s_mean[tid] = mean_[tid];
    }
    __syncthreads();

    const float K = 128.0f / 255.0f;
    float E[4][8], O[4][8];

    // ---- Tile A: consume + refill slots with tile B (8 groups stay in flight)
    #pragma unroll
    for (int xp = 0; xp < 4; xp++)
        #pragma unroll
        for (int y = 0; y < 8; y++) { E[xp][y] = K; O[xp][y] = 0.0f; }

    consume_chunk<0, 7>(sbuf, sb, srcB, s_hx, s_hy, s_std, s_mean, tid, warp, lane, E, O);
    consume_chunk<1, 7>(sbuf, sb, srcB, s_hx, s_hy, s_std, s_mean, tid, warp, lane, E, O);
    consume_chunk<2, 7>(sbuf, sb, srcB, s_hx, s_hy, s_std, s_mean, tid, warp, lane, E, O);
    consume_chunk<3, 7>(sbuf, sb, srcB, s_hx, s_hy, s_std, s_mean, tid, warp, lane, E, O);
    consume_chunk<4, 7>(sbuf, sb, srcB, s_hx, s_hy, s_std, s_mean, tid, warp, lane, E, O);
    consume_chunk<5, 7>(sbuf, sb, srcB, s_hx, s_hy, s_std, s_mean, tid, warp, lane, E, O);
    consume_chunk<6, 7>(sbuf, sb, srcB, s_hx, s_hy, s_std, s_mean, tid, warp, lane, E, O);
    consume_chunk<7, 7>(sbuf, sb, srcB, s_hx, s_hy, s_std, s_mean, tid, warp, lane, E, O);

    // Stores of A overlap tile B's in-flight reads.
    store_block(out, gidA, E, O);

    // ---- Tile B: drain (wait bound decreases; empty commits inside keep math valid)
    #pragma unroll
    for (int xp = 0; xp < 4; xp++)
        #pragma unroll
        for (int y = 0; y < 8; y++) { E[xp][y] = K; O[xp][y] = 0.0f; }

    consume_chunk<0, 7>(sbuf, sb, nullptr, s_hx, s_hy, s_std, s_mean, tid, warp, lane, E, O);
    consume_chunk<1, 6>(sbuf, sb, nullptr, s_hx, s_hy, s_std, s_mean, tid, warp, lane, E, O);
    consume_chunk<2, 5>(sbuf, sb, nullptr, s_hx, s_hy, s_std, s_mean, tid, warp, lane, E, O);
    consume_chunk<3, 4>(sbuf, sb, nullptr, s_hx, s_hy, s_std, s_mean, tid, warp, lane, E, O);
    consume_chunk<4, 3>(sbuf, sb, nullptr, s_hx, s_hy, s_std, s_mean, tid, warp, lane, E, O);
    consume_chunk<5, 2>(sbuf, sb, nullptr, s_hx, s_hy, s_std, s_mean, tid, warp, lane, E, O);
    consume_chunk<6, 1>(sbuf, sb, nullptr, s_hx, s_hy, s_std, s_mean, tid, warp, lane, E, O);
    consume_chunk<7, 0>(sbuf, sb, nullptr, s_hx, s_hy, s_std, s_mean, tid, warp, lane, E, O);

    store_block(out, gidB, E, O);
}

extern "C" void kernel_launch(void* const* d_in, const int* in_sizes, int n_in,
                              void* d_out, int out_size)
{
    (void)in_sizes; (void)n_in; (void)out_size;
    const float* dct   = (const float*)d_in[0];
    const float* mean_ = (const float*)d_in[1];
    const float* std_  = (const float*)d_in[2];
    float* out = (float*)d_out;

    static bool attr_set = false;
    if (!attr_set) {
        cudaFuncSetAttribute(idct_kernel,
                             cudaFuncAttributeMaxDynamicSharedMemorySize,
                             SMEM_BYTES);
        attr_set = true;
    }
    // 4096 tiles of 256 blocks, 2 tiles per CTA -> 2048 CTAs.
    idct_kernel<<<2048, 256, SMEM_BYTES>>>(dct, mean_, std_, out);
}

// round 12
// speedup vs baseline: 1.0923x; 1.0923x over previous
#include <cuda_runtime.h>
#include <cstdint>

// dct: [16, 64, 256, 256] fp32, mean/std: [64] fp32, out: [16, 1, 2048, 2048] fp32
#define HW      65536        // 256*256
#define OUTW    2048

// Dynamic smem (floats): sbuf [8 chunks][8 ch][256 pos] + tables
#define SBUF_FLOATS   16384
#define SMEM_FLOATS   (SBUF_FLOATS + 192)
#define SMEM_BYTES    (SMEM_FLOATS * 4)

__device__ __forceinline__ void cp_async16(uint32_t dst, const void* src) {
    asm volatile("cp.async.cg.shared.global [%0], [%1], 16;" :: "r"(dst), "l"(src));
}
__device__ __forceinline__ void cp_commit() {
    asm volatile("cp.async.commit_group;");
}
template <int N>
__device__ __forceinline__ void cp_wait() {
    asm volatile("cp.async.wait_group %0;" :: "n"(N) : "memory");
}

// Consume chunk U (warp-local ordering only: wait_group + syncwarp).
template <int U>
__device__ __forceinline__ void consume_chunk(
    const float* sbuf, const float* s_hx, const float* s_hy,
    const float* s_std, const float* s_mean,
    int tid, float E[4][8], float O[4][8])
{
    cp_wait<7 - U>();
    __syncwarp();      // unit m is written by lane (m&31), read by lanes 4(m&7)..+3

    float t[8];
    #pragma unroll
    for (int v = 0; v < 8; v++)
        t[v] = fmaf(sbuf[U * 2048 + v * 256 + tid],
                    s_std[U * 8 + v], s_mean[U * 8 + v]);

    float ty[8];
    #pragma unroll
    for (int yp = 0; yp < 4; yp++) {
        float te = 0.0f, to = 0.0f;
        #pragma unroll
        for (int vp = 0; vp < 4; vp++) {
            te = fmaf(s_hy[(2 * vp    ) * 4 + yp], t[2 * vp    ], te);
            to = fmaf(s_hy[(2 * vp + 1) * 4 + yp], t[2 * vp + 1], to);
        }
        ty[yp]     = te + to;
        ty[7 - yp] = te - to;
    }

    #pragma unroll
    for (int xp = 0; xp < 4; xp++) {
        float w = s_hx[U * 4 + xp];
        if ((U & 1) == 0) {
            #pragma unroll
            for (int y = 0; y < 8; y++) E[xp][y] = fmaf(w, ty[y], E[xp][y]);
        } else {
            #pragma unroll
            for (int y = 0; y < 8; y++) O[xp][y] = fmaf(w, ty[y], O[xp][y]);
        }
    }
}

__global__ __launch_bounds__(256, 2) void idct_kernel(
    const float* __restrict__ dct,
    const float* __restrict__ mean_,
    const float* __restrict__ std_,
    float* __restrict__ out)
{
    extern __shared__ float smem[];
    float* sbuf   = smem;                      // [8][8][256]
    float* s_hx   = smem + SBUF_FLOATS;        // [8][4]
    float* s_hy   = s_hx + 32;                 // [8][4]
    float* s_std  = s_hy + 32;                 // [64]
    float* s_mean = s_std + 64;                // [64]

    int tid  = threadIdx.x;
    int warp = tid >> 5, lane = tid & 31;

    unsigned gid = blockIdx.x * 256u + (unsigned)tid;
    unsigned b   = gid >> 16;
    unsigned pos = gid & 65535u;                          // h*256 + w
    unsigned wpos = (blockIdx.x * 256u + warp * 32u) & 65535u;  // warp-uniform
    const float* src_w = dct + (size_t)b * 64u * HW + wpos;

    uint32_t sb = (uint32_t)__cvta_generic_to_shared(sbuf);

    // ---- Warp-private prefetch: warp w copies the 64 x 128B segments that
    // cover positions [32w, 32w+32) across all channels. Per chunk (8 ch,
    // 1KB/warp): 64 units of 16B, 2 per lane. Unit m: channel c*8 + (m>>3),
    // float col within warp stripe = (m&7)*4. One commit group per chunk. ----
    #pragma unroll
    for (int c = 0; c < 8; c++) {
        #pragma unroll
        for (int k = 0; k < 2; k++) {
            int m = lane + k * 32;
            const float* g = src_w + (size_t)(c * 8 + (m >> 3)) * HW + (m & 7) * 4;
            cp_async16(sb + (uint32_t)((c * 2048 + (m >> 3) * 256 + warp * 32 + (m & 7) * 4) * 4), g);
        }
        cp_commit();
    }

    // ---- Tables (overlap with copies); single barrier before use ----
    if (tid < 64) {
        int u = tid >> 3, x = tid & 7;
        float c = (u == 0) ? 0.70710678118654752440f : 1.0f;
        float h = cospif((float)((2 * x + 1) * u) * (1.0f / 16.0f));
        float v = 0.5f * c * h;
        if (x < 4) {
            s_hx[u * 4 + x] = v;
            s_hy[u * 4 + x] = v * (1.0f / 255.0f);
        }
        s_std[tid]  = std_[tid];
        s_mean[tid] = mean_[tid];
    }
    __syncthreads();   // tables visible; does NOT drain cp.async groups

    // ---- Accumulators: rows xp = E+O, rows 7-xp = E-O. K folded into E. ----
    const float K = 128.0f / 255.0f;
    float E[4][8], O[4][8];
    #pragma unroll
    for (int xp = 0; xp < 4; xp++)
        #pragma unroll
        for (int y = 0; y < 8; y++) { E[xp][y] = K; O[xp][y] = 0.0f; }

    consume_chunk<0>(sbuf, s_hx, s_hy, s_std, s_mean, tid, E, O);
    consume_chunk<1>(sbuf, s_hx, s_hy, s_std, s_mean, tid, E, O);
    consume_chunk<2>(sbuf, s_hx, s_hy, s_std, s_mean, tid, E, O);
    consume_chunk<3>(sbuf, s_hx, s_hy, s_std, s_mean, tid, E, O);
    consume_chunk<4>(sbuf, s_hx, s_hy, s_std, s_mean, tid, E, O);
    consume_chunk<5>(sbuf, s_hx, s_hy, s_std, s_mean, tid, E, O);
    consume_chunk<6>(sbuf, s_hx, s_hy, s_std, s_mean, tid, E, O);
    consume_chunk<7>(sbuf, s_hx, s_hy, s_std, s_mean, tid, E, O);

    // ---- Write 8x8 pixel block: two streaming STG.128 per row ----
    unsigned hh = pos >> 8, ww = pos & 255u;
    float* dst = out + (size_t)b * ((size_t)OUTW * OUTW)
                     + (size_t)hh * 8 * OUTW + (size_t)ww * 8;

    #pragma unroll
    for (int xp = 0; xp < 4; xp++) {
        float4 a, bq;
        a.x  = E[xp][0] + O[xp][0];  a.y  = E[xp][1] + O[xp][1];
        a.z  = E[xp][2] + O[xp][2];  a.w  = E[xp][3] + O[xp][3];
        bq.x = E[xp][4] + O[xp][4];  bq.y = E[xp][5] + O[xp][5];
        bq.z = E[xp][6] + O[xp][6];  bq.w = E[xp][7] + O[xp][7];
        __stcs((float4*)(dst + (size_t)xp * OUTW),     a);
        __stcs((float4*)(dst + (size_t)xp * OUTW + 4), bq);

        float4 c4, d4;
        c4.x = E[xp][0] - O[xp][0];  c4.y = E[xp][1] - O[xp][1];
        c4.z = E[xp][2] - O[xp][2];  c4.w = E[xp][3] - O[xp][3];
        d4.x = E[xp][4] - O[xp][4];  d4.y = E[xp][5] - O[xp][5];
        d4.z = E[xp][6] - O[xp][6];  d4.w = E[xp][7] - O[xp][7];
        __stcs((float4*)(dst + (size_t)(7 - xp) * OUTW),     c4);
        __stcs((float4*)(dst + (size_t)(7 - xp) * OUTW + 4), d4);
    }
}

extern "C" void kernel_launch(void* const* d_in, const int* in_sizes, int n_in,
                              void* d_out, int out_size)
{
    (void)in_sizes; (void)n_in; (void)out_size;
    const float* dct   = (const float*)d_in[0];
    const float* mean_ = (const float*)d_in[1];
    const float* std_  = (const float*)d_in[2];
    float* out = (float*)d_out;

    static bool attr_set = false;
    if (!attr_set) {
        cudaFuncSetAttribute(idct_kernel,
                             cudaFuncAttributeMaxDynamicSharedMemorySize,
                             SMEM_BYTES);
        attr_set = true;
    }
    // 16*256*256 = 1,048,576 blocks of 8x8 pixels, 1 thread each.
    idct_kernel<<<4096, 256, SMEM_BYTES>>>(dct, mean_, std_, out);
}